// round 8
// baseline (speedup 1.0000x reference)
#include <cuda_runtime.h>
#include <cuda_fp16.h>
#include <math.h>
#include <stdint.h>

// ---------------- problem constants ----------------
#define BATCH   4
#define SEQ     4096
#define DIM     1024
#define DI      2048
#define HGCOLS  4096
#define MROWS   16384
#define NCH     8192
#define CHUNK   128
#define NCHUNK  32

// ---------------- scratch ----------------
__device__ float g_hg[(size_t)MROWS * HGCOLS];        // 256 MB
__device__ __half g_xhi[(size_t)MROWS * DIM];
__device__ __half g_xlo[(size_t)MROWS * DIM];
__device__ __half g_whgT_hi[(size_t)HGCOLS * DIM];    // [N,K]
__device__ __half g_whgT_lo[(size_t)HGCOLS * DIM];
__device__ __half g_woutT_hi[(size_t)DIM * DI];       // [N,K]
__device__ __half g_woutT_lo[(size_t)DIM * DI];
__device__ __half g_hhi[(size_t)MROWS * DI];
__device__ __half g_hlo[(size_t)MROWS * DI];
__device__ float g_A[NCH * NCHUNK];
__device__ float g_M[NCH * NCHUNK];
__device__ float g_W[NCH * NCHUNK];

// ---------------- PTX helpers ----------------
__device__ __forceinline__ uint32_t smem_u32(const void* p) {
    uint32_t a;
    asm("{ .reg .u64 t; cvta.to.shared.u64 t, %1; cvt.u32.u64 %0, t; }" : "=r"(a) : "l"(p));
    return a;
}
__device__ __forceinline__ void cp16(uint32_t dst, const void* src) {
    asm volatile("cp.async.cg.shared.global [%0], [%1], 16;" :: "r"(dst), "l"(src));
}
#define CP_COMMIT() asm volatile("cp.async.commit_group;" ::: "memory")
#define CP_WAIT0()  asm volatile("cp.async.wait_group 0;" ::: "memory")

#define LDSM4(r, a) asm volatile( \
    "ldmatrix.sync.aligned.m8n8.x4.shared.b16 {%0,%1,%2,%3}, [%4];" \
    : "=r"((r)[0]), "=r"((r)[1]), "=r"((r)[2]), "=r"((r)[3]) : "r"(a))
#define LDSM2(r, a) asm volatile( \
    "ldmatrix.sync.aligned.m8n8.x2.shared.b16 {%0,%1}, [%2];" \
    : "=r"((r)[0]), "=r"((r)[1]) : "r"(a))
#define MMA16816(c, a, b) asm volatile( \
    "mma.sync.aligned.m16n8k16.row.col.f32.f16.f16.f32 " \
    "{%0,%1,%2,%3},{%4,%5,%6,%7},{%8,%9},{%0,%1,%2,%3};" \
    : "+f"((c)[0]), "+f"((c)[1]), "+f"((c)[2]), "+f"((c)[3]) \
    : "r"((a)[0]), "r"((a)[1]), "r"((a)[2]), "r"((a)[3]), "r"((b)[0]), "r"((b)[1]))

// ---------------- HMMA GEMM: C[M,N] = A[M,K] @ B[N,K]^T, hi/lo fp16 split ----------------
#define BM 128
#define BN 128
#define BK 32
#define SSTRIDE_H 40                     // halves per smem row (32 + 8 pad)
#define LIMB_BYTES (128 * SSTRIDE_H * 2) // 10240
#define STAGE_BYTES (4 * LIMB_BYTES)     // Ahi, Alo, Bhi, Blo = 40960
#define GEMM_DYNSMEM (2 * STAGE_BYTES)   // 81920

__global__ __launch_bounds__(256, 2)
void hmma_gemm(const __half* __restrict__ Ahi, const __half* __restrict__ Alo,
               const __half* __restrict__ Bhi, const __half* __restrict__ Blo,
               float* __restrict__ C, int N, int K) {
    extern __shared__ char dynsmem[];
    const uint32_t sbase = smem_u32(dynsmem);

    const int tid  = threadIdx.x;
    const int wid  = tid >> 5;
    const int lane = tid & 31;
    const int wm   = wid >> 2;          // 0..1 (64-row slab)
    const int wn   = wid & 3;           // 0..3 (32-col slab)
    const int m0   = blockIdx.y * BM;
    const int n0   = blockIdx.x * BN;
    const int NI   = K / BK;

    const int arow_l = (lane & 7) + ((lane & 8) ? 8 : 0);
    const int acol_l = (lane >> 4) * 8;
    const int blane  = lane & 15;
    const int brow_l = blane & 7;
    const int bcol_l = (blane >> 3) * 8;

    float acc[4][4][4];
    #pragma unroll
    for (int i = 0; i < 4; i++)
        #pragma unroll
        for (int j = 0; j < 4; j++)
            #pragma unroll
            for (int q = 0; q < 4; q++) acc[i][j][q] = 0.f;

    auto prefetch = [&](int it, int s) {
        const uint32_t sb = sbase + s * STAGE_BYTES;
        const int kt = it * BK;
        #pragma unroll
        for (int t = tid; t < 512; t += 256) {
            const int row = t >> 2;
            const int seg = t & 3;
            const uint32_t so = (uint32_t)(row * (SSTRIDE_H * 2) + seg * 16);
            const size_t ga = (size_t)(m0 + row) * K + kt + seg * 8;
            const size_t gb = (size_t)(n0 + row) * K + kt + seg * 8;
            cp16(sb + so,                  Ahi + ga);
            cp16(sb + LIMB_BYTES + so,     Alo + ga);
            cp16(sb + 2 * LIMB_BYTES + so, Bhi + gb);
            cp16(sb + 3 * LIMB_BYTES + so, Blo + gb);
        }
        CP_COMMIT();
    };

    prefetch(0, 0);

    for (int it = 0; it < NI; it++) {
        const int s = it & 1;
        CP_WAIT0();
        __syncthreads();   // single barrier per chunk: proves stage s complete
                           // AND all warps done reading stage s^1 (last read in it-1)
        if (it + 1 < NI) prefetch(it + 1, s ^ 1);

        const uint32_t sAh = sbase + s * STAGE_BYTES;
        const uint32_t sAl = sAh + LIMB_BYTES;
        const uint32_t sBh = sAh + 2 * LIMB_BYTES;
        const uint32_t sBl = sAh + 3 * LIMB_BYTES;

        #pragma unroll
        for (int ks = 0; ks < 2; ks++) {
            uint32_t aoff[4], boff[4];
            #pragma unroll
            for (int mf = 0; mf < 4; mf++)
                aoff[mf] = (uint32_t)((wm * 64 + mf * 16 + arow_l) * (SSTRIDE_H * 2) +
                                      (ks * 16 + acol_l) * 2);
            #pragma unroll
            for (int nf = 0; nf < 4; nf++)
                boff[nf] = (uint32_t)((wn * 32 + nf * 8 + brow_l) * (SSTRIDE_H * 2) +
                                      (ks * 16 + bcol_l) * 2);

            uint32_t af[4][4], bh[4][2], bl[4][2];

            // load Ah, Bh, Bl once
            #pragma unroll
            for (int mf = 0; mf < 4; mf++) LDSM4(af[mf], sAh + aoff[mf]);
            #pragma unroll
            for (int nf = 0; nf < 4; nf++) LDSM2(bh[nf], sBh + boff[nf]);
            #pragma unroll
            for (int nf = 0; nf < 4; nf++) LDSM2(bl[nf], sBl + boff[nf]);

            // term 1: Ah * Bh
            #pragma unroll
            for (int mf = 0; mf < 4; mf++)
                #pragma unroll
                for (int nf = 0; nf < 4; nf++) MMA16816(acc[mf][nf], af[mf], bh[nf]);
            // term 2: Ah * Bl
            #pragma unroll
            for (int mf = 0; mf < 4; mf++)
                #pragma unroll
                for (int nf = 0; nf < 4; nf++) MMA16816(acc[mf][nf], af[mf], bl[nf]);
            // term 3: Al * Bh (Ah dead; reuse its registers)
            #pragma unroll
            for (int mf = 0; mf < 4; mf++) LDSM4(af[mf], sAl + aoff[mf]);
            #pragma unroll
            for (int mf = 0; mf < 4; mf++)
                #pragma unroll
                for (int nf = 0; nf < 4; nf++) MMA16816(acc[mf][nf], af[mf], bh[nf]);
        }
    }

    // epilogue
    #pragma unroll
    for (int mf = 0; mf < 4; mf++) {
        const int r0 = m0 + wm * 64 + mf * 16 + lane / 4;
        #pragma unroll
        for (int nf = 0; nf < 4; nf++) {
            const int col = n0 + wn * 32 + nf * 8 + 2 * (lane % 4);
            *(float2*)(C + (size_t)r0 * N + col) =
                make_float2(acc[mf][nf][0], acc[mf][nf][1]);
            *(float2*)(C + (size_t)(r0 + 8) * N + col) =
                make_float2(acc[mf][nf][2], acc[mf][nf][3]);
        }
    }
}

// ---------------- prep: split / transpose+split ----------------
__global__ __launch_bounds__(256)
void split_plain(const float* __restrict__ in, __half* __restrict__ hi,
                 __half* __restrict__ lo, int n) {
    int i = blockIdx.x * blockDim.x + threadIdx.x;
    if (i >= n) return;
    float v = in[i];
    __half h = __float2half_rn(v);
    hi[i] = h;
    lo[i] = __float2half_rn(v - __half2float(h));
}

__global__ __launch_bounds__(256)
void transpose_split(const float* __restrict__ W, __half* __restrict__ hi,
                     __half* __restrict__ lo, int K, int N) {
    int i = blockIdx.x * blockDim.x + threadIdx.x;
    if (i >= K * N) return;
    int n = i / K, k = i % K;
    float v = W[(size_t)k * N + n];
    __half h = __float2half_rn(v);
    hi[i] = h;
    lo[i] = __float2half_rn(v - __half2float(h));
}

// ---------------- scan (float4 across channels: 4 channels / thread) ----------------
__device__ __forceinline__ void minGRU_terms(float hid, float g, float& lc, float& lv) {
    float sp = log1pf(__expf(-fabsf(g))) + fmaxf(g, 0.f);
    lc = -sp;
    float log_z = g - sp;
    lv = __logf(fmaxf(hid, 0.f) + 0.5f) + log_z;
}

#define DI4 (DI / 4)   // 512

__global__ __launch_bounds__(256)
void scan_pass1() {
    int tid = blockIdx.x * blockDim.x + threadIdx.x;   // NCH/4 * NCHUNK = 65536
    int e4 = tid % DI4;
    int c  = (tid / DI4) % NCHUNK;
    int b  = tid / (DI4 * NCHUNK);

    const float* base = g_hg + ((size_t)(b * SEQ + c * CHUNK)) * HGCOLS + e4 * 4;
    float a[4], m[4], s[4];
    #pragma unroll
    for (int j = 0; j < 4; j++) { a[j] = 0.f; m[j] = -INFINITY; s[j] = 0.f; }

    for (int t = 0; t < CHUNK; t++) {
        float4 hid = *(const float4*)(base + (size_t)t * HGCOLS);
        float4 gt  = *(const float4*)(base + (size_t)t * HGCOLS + DI);
        float hv[4] = {hid.x, hid.y, hid.z, hid.w};
        float gv[4] = {gt.x, gt.y, gt.z, gt.w};
        #pragma unroll
        for (int j = 0; j < 4; j++) {
            float lc, lv;
            minGRU_terms(hv[j], gv[j], lc, lv);
            a[j] += lc;
            float v = lv - a[j];
            if (v <= m[j]) {
                s[j] += __expf(v - m[j]);
            } else {
                s[j] = s[j] * __expf(m[j] - v) + 1.f;
                m[j] = v;
            }
        }
    }
    int o = (b * NCHUNK + c) * DI + e4 * 4;
    #pragma unroll
    for (int j = 0; j < 4; j++) {
        g_A[o + j] = a[j];
        g_M[o + j] = m[j] + __logf(s[j]);
    }
}

__global__ __launch_bounds__(256)
void scan_mid() {
    int tid = blockIdx.x * blockDim.x + threadIdx.x;   // NCH/4 = 2048
    int e4 = tid % DI4;
    int b  = tid / DI4;
    float W[4] = {-INFINITY, -INFINITY, -INFINITY, -INFINITY};
    for (int c = 0; c < NCHUNK; c++) {
        int o = (b * NCHUNK + c) * DI + e4 * 4;
        float4 Av = *(const float4*)(g_A + o);
        float4 Mv = *(const float4*)(g_M + o);
        *(float4*)(g_W + o) = make_float4(W[0], W[1], W[2], W[3]);
        float Aa[4] = {Av.x, Av.y, Av.z, Av.w};
        float Mm[4] = {Mv.x, Mv.y, Mv.z, Mv.w};
        #pragma unroll
        for (int j = 0; j < 4; j++) {
            float mx = fmaxf(W[j], Mm[j]);
            float mn = fminf(W[j], Mm[j]);
            float r = (mx == -INFINITY) ? -INFINITY : mx + log1pf(__expf(mn - mx));
            W[j] = Aa[j] + r;
        }
    }
}

__global__ __launch_bounds__(256)
void scan_pass2() {
    int tid = blockIdx.x * blockDim.x + threadIdx.x;   // 65536
    int e4 = tid % DI4;
    int c  = (tid / DI4) % NCHUNK;
    int b  = tid / (DI4 * NCHUNK);

    const float* base = g_hg + ((size_t)(b * SEQ + c * CHUNK)) * HGCOLS + e4 * 4;
    size_t hidx = ((size_t)(b * SEQ + c * CHUNK)) * DI + e4 * 4;

    int wo = (b * NCHUNK + c) * DI + e4 * 4;
    float4 Wv = *(const float4*)(g_W + wo);
    float W[4] = {Wv.x, Wv.y, Wv.z, Wv.w};

    float a[4], m[4], s[4];
    #pragma unroll
    for (int j = 0; j < 4; j++) { a[j] = 0.f; m[j] = -INFINITY; s[j] = 0.f; }

    for (int t = 0; t < CHUNK; t++) {
        float4 hid = *(const float4*)(base + (size_t)t * HGCOLS);
        float4 gt  = *(const float4*)(base + (size_t)t * HGCOLS + DI);
        float hvv[4] = {hid.x, hid.y, hid.z, hid.w};
        float gvv[4] = {gt.x, gt.y, gt.z, gt.w};
        __half hr[4], lr[4];
        #pragma unroll
        for (int j = 0; j < 4; j++) {
            float lc, lv;
            minGRU_terms(hvv[j], gvv[j], lc, lv);
            a[j] += lc;
            float v = lv - a[j];
            if (v <= m[j]) {
                s[j] += __expf(v - m[j]);
            } else {
                s[j] = s[j] * __expf(m[j] - v) + 1.f;
                m[j] = v;
            }
            float hval = __expf(a[j] + W[j]) + __expf(a[j] + m[j]) * s[j];
            hr[j] = __float2half_rn(hval);
            lr[j] = __float2half_rn(hval - __half2float(hr[j]));
        }
        // 8-byte vectorized stores of 4 halves
        *(uint2*)(g_hhi + hidx + (size_t)t * DI) =
            make_uint2(((uint32_t)__half_as_ushort(hr[1]) << 16) | __half_as_ushort(hr[0]),
                       ((uint32_t)__half_as_ushort(hr[3]) << 16) | __half_as_ushort(hr[2]));
        *(uint2*)(g_hlo + hidx + (size_t)t * DI) =
            make_uint2(((uint32_t)__half_as_ushort(lr[1]) << 16) | __half_as_ushort(lr[0]),
                       ((uint32_t)__half_as_ushort(lr[3]) << 16) | __half_as_ushort(lr[2]));
    }
}

// ---------------- launch ----------------
extern "C" void kernel_launch(void* const* d_in, const int* in_sizes, int n_in,
                              void* d_out, int out_size) {
    const float* x     = (const float*)d_in[0];
    const float* W_hg  = (const float*)d_in[1];
    const float* W_out = (const float*)d_in[2];
    float* out = (float*)d_out;

    float* hg_ptr;
    __half *xhi, *xlo, *whgT_hi, *whgT_lo, *woutT_hi, *woutT_lo, *hhi, *hlo;
    cudaGetSymbolAddress((void**)&hg_ptr, g_hg);
    cudaGetSymbolAddress((void**)&xhi, g_xhi);
    cudaGetSymbolAddress((void**)&xlo, g_xlo);
    cudaGetSymbolAddress((void**)&whgT_hi, g_whgT_hi);
    cudaGetSymbolAddress((void**)&whgT_lo, g_whgT_lo);
    cudaGetSymbolAddress((void**)&woutT_hi, g_woutT_hi);
    cudaGetSymbolAddress((void**)&woutT_lo, g_woutT_lo);
    cudaGetSymbolAddress((void**)&hhi, g_hhi);
    cudaGetSymbolAddress((void**)&hlo, g_hlo);

    cudaFuncSetAttribute(hmma_gemm, cudaFuncAttributeMaxDynamicSharedMemorySize, GEMM_DYNSMEM);

    split_plain<<<(MROWS * DIM + 255) / 256, 256>>>(x, xhi, xlo, MROWS * DIM);
    transpose_split<<<(DIM * HGCOLS + 255) / 256, 256>>>(W_hg, whgT_hi, whgT_lo, DIM, HGCOLS);
    transpose_split<<<(DI * DIM + 255) / 256, 256>>>(W_out, woutT_hi, woutT_lo, DI, DIM);

    // GEMM1: hg[16384,4096] = x @ W_hg
    {
        dim3 grid(HGCOLS / BN, MROWS / BM);
        hmma_gemm<<<grid, 256, GEMM_DYNSMEM>>>(xhi, xlo, whgT_hi, whgT_lo, hg_ptr, HGCOLS, DIM);
    }

    scan_pass1<<<(NCH / 4 * NCHUNK) / 256, 256>>>();
    scan_mid<<<(NCH / 4) / 256, 256>>>();
    scan_pass2<<<(NCH / 4 * NCHUNK) / 256, 256>>>();

    // GEMM2: out[16384,1024] = h @ W_out
    {
        dim3 grid(DIM / BN, MROWS / BM);
        hmma_gemm<<<grid, 256, GEMM_DYNSMEM>>>(hhi, hlo, woutT_hi, woutT_lo, out, DIM, DI);
    }
}

// round 9
// speedup vs baseline: 1.0864x; 1.0864x over previous
#include <cuda_runtime.h>
#include <cuda_fp16.h>
#include <math.h>
#include <stdint.h>

// ---------------- problem constants ----------------
#define BATCH   4
#define SEQ     4096
#define DIM     1024
#define DI      2048
#define HGCOLS  4096
#define MROWS   16384
#define NCH     8192
#define CHUNK   128
#define NCHUNK  32

// ---------------- scratch ----------------
__device__ float g_hg[(size_t)MROWS * HGCOLS];        // 256 MB
__device__ __half g_xhi[(size_t)MROWS * DIM];
__device__ __half g_xlo[(size_t)MROWS * DIM];
__device__ __half g_whgT_hi[(size_t)HGCOLS * DIM];    // [N,K]
__device__ __half g_whgT_lo[(size_t)HGCOLS * DIM];
__device__ __half g_woutT_hi[(size_t)DIM * DI];       // [N,K]
__device__ __half g_woutT_lo[(size_t)DIM * DI];
__device__ __half g_hhi[(size_t)MROWS * DI];
__device__ __half g_hlo[(size_t)MROWS * DI];
__device__ float g_A[NCH * NCHUNK];
__device__ float g_M[NCH * NCHUNK];
__device__ float g_W[NCH * NCHUNK];

// ---------------- PTX helpers ----------------
__device__ __forceinline__ uint32_t smem_u32(const void* p) {
    uint32_t a;
    asm("{ .reg .u64 t; cvta.to.shared.u64 t, %1; cvt.u32.u64 %0, t; }" : "=r"(a) : "l"(p));
    return a;
}
__device__ __forceinline__ void cp16(uint32_t dst, const void* src) {
    asm volatile("cp.async.cg.shared.global [%0], [%1], 16;" :: "r"(dst), "l"(src));
}
#define CP_COMMIT() asm volatile("cp.async.commit_group;" ::: "memory")
#define CP_WAIT0()  asm volatile("cp.async.wait_group 0;" ::: "memory")

#define LDSM4(r, a) asm volatile( \
    "ldmatrix.sync.aligned.m8n8.x4.shared.b16 {%0,%1,%2,%3}, [%4];" \
    : "=r"((r)[0]), "=r"((r)[1]), "=r"((r)[2]), "=r"((r)[3]) : "r"(a))
#define LDSM2(r, a) asm volatile( \
    "ldmatrix.sync.aligned.m8n8.x2.shared.b16 {%0,%1}, [%2];" \
    : "=r"((r)[0]), "=r"((r)[1]) : "r"(a))
#define MMA16816(c, a, b) asm volatile( \
    "mma.sync.aligned.m16n8k16.row.col.f32.f16.f16.f32 " \
    "{%0,%1,%2,%3},{%4,%5,%6,%7},{%8,%9},{%0,%1,%2,%3};" \
    : "+f"((c)[0]), "+f"((c)[1]), "+f"((c)[2]), "+f"((c)[3]) \
    : "r"((a)[0]), "r"((a)[1]), "r"((a)[2]), "r"((a)[3]), "r"((b)[0]), "r"((b)[1]))

// ---------------- HMMA GEMM: C[M,N] = A[M,K] @ B[N,K]^T, hi/lo fp16 split ----------------
#define BM 128
#define BN 128
#define BK 32
#define SSTRIDE_H 40                     // halves per smem row (32 + 8 pad)
#define LIMB_BYTES (128 * SSTRIDE_H * 2) // 10240
#define STAGE_BYTES (4 * LIMB_BYTES)     // Ahi, Alo, Bhi, Blo = 40960
#define GEMM_DYNSMEM (2 * STAGE_BYTES)   // 81920

__global__ __launch_bounds__(256, 2)
void hmma_gemm(const __half* __restrict__ Ahi, const __half* __restrict__ Alo,
               const __half* __restrict__ Bhi, const __half* __restrict__ Blo,
               float* __restrict__ C, int N, int K) {
    extern __shared__ char dynsmem[];
    const uint32_t sbase = smem_u32(dynsmem);

    const int tid  = threadIdx.x;
    const int wid  = tid >> 5;
    const int lane = tid & 31;
    const int wm   = wid >> 2;
    const int wn   = wid & 3;
    const int m0   = blockIdx.y * BM;
    const int n0   = blockIdx.x * BN;
    const int NI   = K / BK;

    const int arow_l = (lane & 7) + ((lane & 8) ? 8 : 0);
    const int acol_l = (lane >> 4) * 8;
    const int blane  = lane & 15;
    const int brow_l = blane & 7;
    const int bcol_l = (blane >> 3) * 8;

    float acc[4][4][4];
    #pragma unroll
    for (int i = 0; i < 4; i++)
        #pragma unroll
        for (int j = 0; j < 4; j++)
            #pragma unroll
            for (int q = 0; q < 4; q++) acc[i][j][q] = 0.f;

    auto prefetch = [&](int it, int s) {
        const uint32_t sb = sbase + s * STAGE_BYTES;
        const int kt = it * BK;
        #pragma unroll
        for (int t = tid; t < 512; t += 256) {
            const int row = t >> 2;
            const int seg = t & 3;
            const uint32_t so = (uint32_t)(row * (SSTRIDE_H * 2) + seg * 16);
            const size_t ga = (size_t)(m0 + row) * K + kt + seg * 8;
            const size_t gb = (size_t)(n0 + row) * K + kt + seg * 8;
            cp16(sb + so,                  Ahi + ga);
            cp16(sb + LIMB_BYTES + so,     Alo + ga);
            cp16(sb + 2 * LIMB_BYTES + so, Bhi + gb);
            cp16(sb + 3 * LIMB_BYTES + so, Blo + gb);
        }
        CP_COMMIT();
    };

    prefetch(0, 0);

    for (int it = 0; it < NI; it++) {
        const int s = it & 1;
        CP_WAIT0();
        __syncthreads();   // single barrier: stage s loaded AND stage s^1 free
        if (it + 1 < NI) prefetch(it + 1, s ^ 1);

        const uint32_t sAh = sbase + s * STAGE_BYTES;
        const uint32_t sAl = sAh + LIMB_BYTES;
        const uint32_t sBh = sAh + 2 * LIMB_BYTES;
        const uint32_t sBl = sAh + 3 * LIMB_BYTES;

        #pragma unroll
        for (int ks = 0; ks < 2; ks++) {
            uint32_t aoff[4], boff[4];
            #pragma unroll
            for (int mf = 0; mf < 4; mf++)
                aoff[mf] = (uint32_t)((wm * 64 + mf * 16 + arow_l) * (SSTRIDE_H * 2) +
                                      (ks * 16 + acol_l) * 2);
            #pragma unroll
            for (int nf = 0; nf < 4; nf++)
                boff[nf] = (uint32_t)((wn * 32 + nf * 8 + brow_l) * (SSTRIDE_H * 2) +
                                      (ks * 16 + bcol_l) * 2);

            uint32_t af[4][4], bh[4][2], bl[4][2];

            #pragma unroll
            for (int mf = 0; mf < 4; mf++) LDSM4(af[mf], sAh + aoff[mf]);
            #pragma unroll
            for (int nf = 0; nf < 4; nf++) LDSM2(bh[nf], sBh + boff[nf]);
            #pragma unroll
            for (int nf = 0; nf < 4; nf++) LDSM2(bl[nf], sBl + boff[nf]);

            // Ah * Bh
            #pragma unroll
            for (int mf = 0; mf < 4; mf++)
                #pragma unroll
                for (int nf = 0; nf < 4; nf++) MMA16816(acc[mf][nf], af[mf], bh[nf]);
            // Ah * Bl
            #pragma unroll
            for (int mf = 0; mf < 4; mf++)
                #pragma unroll
                for (int nf = 0; nf < 4; nf++) MMA16816(acc[mf][nf], af[mf], bl[nf]);
            // Al * Bh
            #pragma unroll
            for (int mf = 0; mf < 4; mf++) LDSM4(af[mf], sAl + aoff[mf]);
            #pragma unroll
            for (int mf = 0; mf < 4; mf++)
                #pragma unroll
                for (int nf = 0; nf < 4; nf++) MMA16816(acc[mf][nf], af[mf], bh[nf]);
        }
    }

    // epilogue
    #pragma unroll
    for (int mf = 0; mf < 4; mf++) {
        const int r0 = m0 + wm * 64 + mf * 16 + lane / 4;
        #pragma unroll
        for (int nf = 0; nf < 4; nf++) {
            const int col = n0 + wn * 32 + nf * 8 + 2 * (lane % 4);
            *(float2*)(C + (size_t)r0 * N + col) =
                make_float2(acc[mf][nf][0], acc[mf][nf][1]);
            *(float2*)(C + (size_t)(r0 + 8) * N + col) =
                make_float2(acc[mf][nf][2], acc[mf][nf][3]);
        }
    }
}

// ---------------- prep: split / tiled transpose+split ----------------
__global__ __launch_bounds__(256)
void split_plain(const float* __restrict__ in, __half* __restrict__ hi,
                 __half* __restrict__ lo, int n) {
    int i = blockIdx.x * blockDim.x + threadIdx.x;
    if (i >= n) return;
    float v = in[i];
    __half h = __float2half_rn(v);
    hi[i] = h;
    lo[i] = __float2half_rn(v - __half2float(h));
}

// W[K,N] row-major -> out[N,K] row-major, 32x32 smem tiles, both sides coalesced
__global__ __launch_bounds__(256)
void transpose_split_tiled(const float* __restrict__ W, __half* __restrict__ hi,
                           __half* __restrict__ lo, int K, int N) {
    __shared__ float tile[32][33];
    const int k0 = blockIdx.y * 32;
    const int n0 = blockIdx.x * 32;
    const int tx = threadIdx.x & 31;
    const int ty = threadIdx.x >> 5;   // 0..7

    #pragma unroll
    for (int r = 0; r < 4; r++) {
        const int k = k0 + ty + r * 8;
        tile[ty + r * 8][tx] = W[(size_t)k * N + n0 + tx];
    }
    __syncthreads();
    #pragma unroll
    for (int r = 0; r < 4; r++) {
        const int n = n0 + ty + r * 8;
        float v = tile[tx][ty + r * 8];
        __half h = __float2half_rn(v);
        hi[(size_t)n * K + k0 + tx] = h;
        lo[(size_t)n * K + k0 + tx] = __float2half_rn(v - __half2float(h));
    }
}

// ---------------- scan (scalar, round-7 proven form) ----------------
__device__ __forceinline__ void minGRU_terms(float hid, float g, float& lc, float& lv) {
    float sp = log1pf(__expf(-fabsf(g))) + fmaxf(g, 0.f);
    lc = -sp;
    float log_z = g - sp;
    lv = __logf(fmaxf(hid, 0.f) + 0.5f) + log_z;
}

__global__ __launch_bounds__(256)
void scan_pass1() {
    int tid = blockIdx.x * blockDim.x + threadIdx.x;
    int e = tid % DI;
    int c = (tid / DI) % NCHUNK;
    int b = tid / (DI * NCHUNK);

    const float* base = g_hg + ((size_t)(b * SEQ + c * CHUNK)) * HGCOLS + e;
    float a = 0.f, m = -INFINITY, s = 0.f;
    for (int t = 0; t < CHUNK; t++) {
        float hid = base[(size_t)t * HGCOLS];
        float g   = base[(size_t)t * HGCOLS + DI];
        float lc, lv;
        minGRU_terms(hid, g, lc, lv);
        a += lc;
        float v = lv - a;
        if (v <= m) {
            s += __expf(v - m);
        } else {
            s = s * __expf(m - v) + 1.f;
            m = v;
        }
    }
    int o = (b * NCHUNK + c) * DI + e;
    g_A[o] = a;
    g_M[o] = m + __logf(s);
}

__global__ __launch_bounds__(256)
void scan_mid() {
    int tid = blockIdx.x * blockDim.x + threadIdx.x;
    int e = tid % DI;
    int b = tid / DI;
    float W = -INFINITY;
    for (int c = 0; c < NCHUNK; c++) {
        int o = (b * NCHUNK + c) * DI + e;
        g_W[o] = W;
        float A = g_A[o], M = g_M[o];
        float mx = fmaxf(W, M);
        float mn = fminf(W, M);
        float r = (mx == -INFINITY) ? -INFINITY : mx + log1pf(__expf(mn - mx));
        W = A + r;
    }
}

__global__ __launch_bounds__(256)
void scan_pass2() {
    int tid = blockIdx.x * blockDim.x + threadIdx.x;
    int e = tid % DI;
    int c = (tid / DI) % NCHUNK;
    int b = tid / (DI * NCHUNK);

    const float* base = g_hg + ((size_t)(b * SEQ + c * CHUNK)) * HGCOLS + e;
    size_t hidx = ((size_t)(b * SEQ + c * CHUNK)) * DI + e;
    float W = g_W[(b * NCHUNK + c) * DI + e];

    float a = 0.f, m = -INFINITY, s = 0.f;
    for (int t = 0; t < CHUNK; t++) {
        float hid = base[(size_t)t * HGCOLS];
        float g   = base[(size_t)t * HGCOLS + DI];
        float lc, lv;
        minGRU_terms(hid, g, lc, lv);
        a += lc;
        float v = lv - a;
        if (v <= m) {
            s += __expf(v - m);
        } else {
            s = s * __expf(m - v) + 1.f;
            m = v;
        }
        float hv = __expf(a + W) + __expf(a + m) * s;
        __half hb = __float2half_rn(hv);
        g_hhi[hidx + (size_t)t * DI] = hb;
        g_hlo[hidx + (size_t)t * DI] = __float2half_rn(hv - __half2float(hb));
    }
}

// ---------------- launch ----------------
extern "C" void kernel_launch(void* const* d_in, const int* in_sizes, int n_in,
                              void* d_out, int out_size) {
    const float* x     = (const float*)d_in[0];
    const float* W_hg  = (const float*)d_in[1];
    const float* W_out = (const float*)d_in[2];
    float* out = (float*)d_out;

    float* hg_ptr;
    __half *xhi, *xlo, *whgT_hi, *whgT_lo, *woutT_hi, *woutT_lo, *hhi, *hlo;
    cudaGetSymbolAddress((void**)&hg_ptr, g_hg);
    cudaGetSymbolAddress((void**)&xhi, g_xhi);
    cudaGetSymbolAddress((void**)&xlo, g_xlo);
    cudaGetSymbolAddress((void**)&whgT_hi, g_whgT_hi);
    cudaGetSymbolAddress((void**)&whgT_lo, g_whgT_lo);
    cudaGetSymbolAddress((void**)&woutT_hi, g_woutT_hi);
    cudaGetSymbolAddress((void**)&woutT_lo, g_woutT_lo);
    cudaGetSymbolAddress((void**)&hhi, g_hhi);
    cudaGetSymbolAddress((void**)&hlo, g_hlo);

    cudaFuncSetAttribute(hmma_gemm, cudaFuncAttributeMaxDynamicSharedMemorySize, GEMM_DYNSMEM);

    split_plain<<<(MROWS * DIM + 255) / 256, 256>>>(x, xhi, xlo, MROWS * DIM);
    {
        dim3 g1(HGCOLS / 32, DIM / 32);
        transpose_split_tiled<<<g1, 256>>>(W_hg, whgT_hi, whgT_lo, DIM, HGCOLS);
        dim3 g2(DIM / 32, DI / 32);
        transpose_split_tiled<<<g2, 256>>>(W_out, woutT_hi, woutT_lo, DI, DIM);
    }

    // GEMM1: hg[16384,4096] = x @ W_hg
    {
        dim3 grid(HGCOLS / BN, MROWS / BM);
        hmma_gemm<<<grid, 256, GEMM_DYNSMEM>>>(xhi, xlo, whgT_hi, whgT_lo, hg_ptr, HGCOLS, DIM);
    }

    scan_pass1<<<(NCH * NCHUNK) / 256, 256>>>();
    scan_mid<<<NCH / 256, 256>>>();
    scan_pass2<<<(NCH * NCHUNK) / 256, 256>>>();

    // GEMM2: out[16384,1024] = h @ W_out
    {
        dim3 grid(DIM / BN, MROWS / BM);
        hmma_gemm<<<grid, 256, GEMM_DYNSMEM>>>(hhi, hlo, woutT_hi, woutT_lo, out, DIM, DI);
    }
}

// round 10
// speedup vs baseline: 1.4549x; 1.3392x over previous
#include <cuda_runtime.h>
#include <cuda_fp16.h>
#include <math.h>
#include <stdint.h>

// ---------------- problem constants ----------------
#define BATCH   4
#define SEQ     4096
#define DIM     1024
#define DI      2048
#define HGCOLS  4096
#define MROWS   16384
#define NCH     8192
#define CHUNK   128
#define NCHUNK  32

// ---------------- scratch ----------------
__device__ float g_hg[(size_t)MROWS * HGCOLS];        // 256 MB
__device__ __half g_xhi[(size_t)MROWS * DIM];
__device__ __half g_whgT_hi[(size_t)HGCOLS * DIM];    // [N,K]
__device__ __half g_whgT_lo[(size_t)HGCOLS * DIM];
__device__ __half g_woutT_hi[(size_t)DIM * DI];       // [N,K]
__device__ __half g_woutT_lo[(size_t)DIM * DI];
__device__ __half g_hhi[(size_t)MROWS * DI];
__device__ float g_A[NCH * NCHUNK];
__device__ float g_M[NCH * NCHUNK];
__device__ float g_W[NCH * NCHUNK];

// ---------------- PTX helpers ----------------
__device__ __forceinline__ uint32_t smem_u32(const void* p) {
    uint32_t a;
    asm("{ .reg .u64 t; cvta.to.shared.u64 t, %1; cvt.u32.u64 %0, t; }" : "=r"(a) : "l"(p));
    return a;
}
__device__ __forceinline__ void cp16(uint32_t dst, const void* src) {
    asm volatile("cp.async.cg.shared.global [%0], [%1], 16;" :: "r"(dst), "l"(src));
}
#define CP_COMMIT() asm volatile("cp.async.commit_group;" ::: "memory")
#define CP_WAIT0()  asm volatile("cp.async.wait_group 0;" ::: "memory")

#define LDSM4(r, a) asm volatile( \
    "ldmatrix.sync.aligned.m8n8.x4.shared.b16 {%0,%1,%2,%3}, [%4];" \
    : "=r"((r)[0]), "=r"((r)[1]), "=r"((r)[2]), "=r"((r)[3]) : "r"(a))
#define LDSM2(r, a) asm volatile( \
    "ldmatrix.sync.aligned.m8n8.x2.shared.b16 {%0,%1}, [%2];" \
    : "=r"((r)[0]), "=r"((r)[1]) : "r"(a))
#define MMA16816(c, a, b) asm volatile( \
    "mma.sync.aligned.m16n8k16.row.col.f32.f16.f16.f32 " \
    "{%0,%1,%2,%3},{%4,%5,%6,%7},{%8,%9},{%0,%1,%2,%3};" \
    : "+f"((c)[0]), "+f"((c)[1]), "+f"((c)[2]), "+f"((c)[3]) \
    : "r"((a)[0]), "r"((a)[1]), "r"((a)[2]), "r"((a)[3]), "r"((b)[0]), "r"((b)[1]))

// ---------------- HMMA GEMM: C[M,N] = A[M,K] @ (Bhi+Blo)[N,K]^T ----------------
#define BM 128
#define BN 128
#define BK 32
#define SSTRIDE_H 40                     // halves per smem row (32 + 8 pad)
#define LIMB_BYTES (128 * SSTRIDE_H * 2) // 10240
#define STAGE_BYTES (3 * LIMB_BYTES)     // Ah, Bhi, Blo = 30720
#define GEMM_DYNSMEM (2 * STAGE_BYTES)   // 61440

__global__ __launch_bounds__(256, 2)
void hmma_gemm(const __half* __restrict__ Ahi,
               const __half* __restrict__ Bhi, const __half* __restrict__ Blo,
               float* __restrict__ C, int N, int K) {
    extern __shared__ char dynsmem[];
    const uint32_t sbase = smem_u32(dynsmem);

    const int tid  = threadIdx.x;
    const int wid  = tid >> 5;
    const int lane = tid & 31;
    const int wm   = wid >> 2;
    const int wn   = wid & 3;
    const int m0   = blockIdx.y * BM;
    const int n0   = blockIdx.x * BN;
    const int NI   = K / BK;

    const int arow_l = (lane & 7) + ((lane & 8) ? 8 : 0);
    const int acol_l = (lane >> 4) * 8;
    const int blane  = lane & 15;
    const int brow_l = blane & 7;
    const int bcol_l = (blane >> 3) * 8;

    float acc[4][4][4];
    #pragma unroll
    for (int i = 0; i < 4; i++)
        #pragma unroll
        for (int j = 0; j < 4; j++)
            #pragma unroll
            for (int q = 0; q < 4; q++) acc[i][j][q] = 0.f;

    auto prefetch = [&](int it, int s) {
        const uint32_t sb = sbase + s * STAGE_BYTES;
        const int kt = it * BK;
        #pragma unroll
        for (int t = tid; t < 512; t += 256) {
            const int row = t >> 2;
            const int seg = t & 3;
            const uint32_t so = (uint32_t)(row * (SSTRIDE_H * 2) + seg * 16);
            const size_t ga = (size_t)(m0 + row) * K + kt + seg * 8;
            const size_t gb = (size_t)(n0 + row) * K + kt + seg * 8;
            cp16(sb + so,                  Ahi + ga);
            cp16(sb + LIMB_BYTES + so,     Bhi + gb);
            cp16(sb + 2 * LIMB_BYTES + so, Blo + gb);
        }
        CP_COMMIT();
    };

    prefetch(0, 0);

    for (int it = 0; it < NI; it++) {
        const int s = it & 1;
        CP_WAIT0();
        __syncthreads();   // single barrier: stage s loaded AND stage s^1 free
        if (it + 1 < NI) prefetch(it + 1, s ^ 1);

        const uint32_t sAh = sbase + s * STAGE_BYTES;
        const uint32_t sBh = sAh + LIMB_BYTES;
        const uint32_t sBl = sAh + 2 * LIMB_BYTES;

        #pragma unroll
        for (int ks = 0; ks < 2; ks++) {
            uint32_t aoff[4], boff[4];
            #pragma unroll
            for (int mf = 0; mf < 4; mf++)
                aoff[mf] = (uint32_t)((wm * 64 + mf * 16 + arow_l) * (SSTRIDE_H * 2) +
                                      (ks * 16 + acol_l) * 2);
            #pragma unroll
            for (int nf = 0; nf < 4; nf++)
                boff[nf] = (uint32_t)((wn * 32 + nf * 8 + brow_l) * (SSTRIDE_H * 2) +
                                      (ks * 16 + bcol_l) * 2);

            uint32_t af[4][4], bh[4][2], bl[4][2];

            #pragma unroll
            for (int mf = 0; mf < 4; mf++) LDSM4(af[mf], sAh + aoff[mf]);
            #pragma unroll
            for (int nf = 0; nf < 4; nf++) LDSM2(bh[nf], sBh + boff[nf]);
            #pragma unroll
            for (int nf = 0; nf < 4; nf++) LDSM2(bl[nf], sBl + boff[nf]);

            // Ah * Bh
            #pragma unroll
            for (int mf = 0; mf < 4; mf++)
                #pragma unroll
                for (int nf = 0; nf < 4; nf++) MMA16816(acc[mf][nf], af[mf], bh[nf]);
            // Ah * Bl
            #pragma unroll
            for (int mf = 0; mf < 4; mf++)
                #pragma unroll
                for (int nf = 0; nf < 4; nf++) MMA16816(acc[mf][nf], af[mf], bl[nf]);
        }
    }

    // epilogue
    #pragma unroll
    for (int mf = 0; mf < 4; mf++) {
        const int r0 = m0 + wm * 64 + mf * 16 + lane / 4;
        #pragma unroll
        for (int nf = 0; nf < 4; nf++) {
            const int col = n0 + wn * 32 + nf * 8 + 2 * (lane % 4);
            *(float2*)(C + (size_t)r0 * N + col) =
                make_float2(acc[mf][nf][0], acc[mf][nf][1]);
            *(float2*)(C + (size_t)(r0 + 8) * N + col) =
                make_float2(acc[mf][nf][2], acc[mf][nf][3]);
        }
    }
}

// ---------------- prep ----------------
__global__ __launch_bounds__(256)
void cast_hi(const float* __restrict__ in, __half* __restrict__ hi, int n) {
    int i = blockIdx.x * blockDim.x + threadIdx.x;
    if (i >= n) return;
    hi[i] = __float2half_rn(in[i]);
}

// W[K,N] row-major -> out[N,K] row-major, 32x32 smem tiles, both sides coalesced
__global__ __launch_bounds__(256)
void transpose_split_tiled(const float* __restrict__ W, __half* __restrict__ hi,
                           __half* __restrict__ lo, int K, int N) {
    __shared__ float tile[32][33];
    const int k0 = blockIdx.y * 32;
    const int n0 = blockIdx.x * 32;
    const int tx = threadIdx.x & 31;
    const int ty = threadIdx.x >> 5;   // 0..7

    #pragma unroll
    for (int r = 0; r < 4; r++) {
        const int k = k0 + ty + r * 8;
        tile[ty + r * 8][tx] = W[(size_t)k * N + n0 + tx];
    }
    __syncthreads();
    #pragma unroll
    for (int r = 0; r < 4; r++) {
        const int n = n0 + ty + r * 8;
        float v = tile[tx][ty + r * 8];
        __half h = __float2half_rn(v);
        hi[(size_t)n * K + k0 + tx] = h;
        lo[(size_t)n * K + k0 + tx] = __float2half_rn(v - __half2float(h));
    }
}

// ---------------- scan (scalar, proven form) ----------------
__device__ __forceinline__ void minGRU_terms(float hid, float g, float& lc, float& lv) {
    float sp = log1pf(__expf(-fabsf(g))) + fmaxf(g, 0.f);
    lc = -sp;
    float log_z = g - sp;
    lv = __logf(fmaxf(hid, 0.f) + 0.5f) + log_z;
}

__global__ __launch_bounds__(256)
void scan_pass1() {
    int tid = blockIdx.x * blockDim.x + threadIdx.x;
    int e = tid % DI;
    int c = (tid / DI) % NCHUNK;
    int b = tid / (DI * NCHUNK);

    const float* base = g_hg + ((size_t)(b * SEQ + c * CHUNK)) * HGCOLS + e;
    float a = 0.f, m = -INFINITY, s = 0.f;
    for (int t = 0; t < CHUNK; t++) {
        float hid = base[(size_t)t * HGCOLS];
        float g   = base[(size_t)t * HGCOLS + DI];
        float lc, lv;
        minGRU_terms(hid, g, lc, lv);
        a += lc;
        float v = lv - a;
        if (v <= m) {
            s += __expf(v - m);
        } else {
            s = s * __expf(m - v) + 1.f;
            m = v;
        }
    }
    int o = (b * NCHUNK + c) * DI + e;
    g_A[o] = a;
    g_M[o] = m + __logf(s);
}

__global__ __launch_bounds__(256)
void scan_mid() {
    int tid = blockIdx.x * blockDim.x + threadIdx.x;
    int e = tid % DI;
    int b = tid / DI;
    float W = -INFINITY;
    for (int c = 0; c < NCHUNK; c++) {
        int o = (b * NCHUNK + c) * DI + e;
        g_W[o] = W;
        float A = g_A[o], M = g_M[o];
        float mx = fmaxf(W, M);
        float mn = fminf(W, M);
        float r = (mx == -INFINITY) ? -INFINITY : mx + log1pf(__expf(mn - mx));
        W = A + r;
    }
}

__global__ __launch_bounds__(256)
void scan_pass2() {
    int tid = blockIdx.x * blockDim.x + threadIdx.x;
    int e = tid % DI;
    int c = (tid / DI) % NCHUNK;
    int b = tid / (DI * NCHUNK);

    const float* base = g_hg + ((size_t)(b * SEQ + c * CHUNK)) * HGCOLS + e;
    size_t hidx = ((size_t)(b * SEQ + c * CHUNK)) * DI + e;
    float W = g_W[(b * NCHUNK + c) * DI + e];

    float a = 0.f, m = -INFINITY, s = 0.f;
    for (int t = 0; t < CHUNK; t++) {
        float hid = base[(size_t)t * HGCOLS];
        float g   = base[(size_t)t * HGCOLS + DI];
        float lc, lv;
        minGRU_terms(hid, g, lc, lv);
        a += lc;
        float v = lv - a;
        if (v <= m) {
            s += __expf(v - m);
        } else {
            s = s * __expf(m - v) + 1.f;
            m = v;
        }
        float hv = __expf(a + W) + __expf(a + m) * s;
        g_hhi[hidx + (size_t)t * DI] = __float2half_rn(hv);
    }
}

// ---------------- launch ----------------
extern "C" void kernel_launch(void* const* d_in, const int* in_sizes, int n_in,
                              void* d_out, int out_size) {
    const float* x     = (const float*)d_in[0];
    const float* W_hg  = (const float*)d_in[1];
    const float* W_out = (const float*)d_in[2];
    float* out = (float*)d_out;

    float* hg_ptr;
    __half *xhi, *whgT_hi, *whgT_lo, *woutT_hi, *woutT_lo, *hhi;
    cudaGetSymbolAddress((void**)&hg_ptr, g_hg);
    cudaGetSymbolAddress((void**)&xhi, g_xhi);
    cudaGetSymbolAddress((void**)&whgT_hi, g_whgT_hi);
    cudaGetSymbolAddress((void**)&whgT_lo, g_whgT_lo);
    cudaGetSymbolAddress((void**)&woutT_hi, g_woutT_hi);
    cudaGetSymbolAddress((void**)&woutT_lo, g_woutT_lo);
    cudaGetSymbolAddress((void**)&hhi, g_hhi);

    cudaFuncSetAttribute(hmma_gemm, cudaFuncAttributeMaxDynamicSharedMemorySize, GEMM_DYNSMEM);

    cast_hi<<<(MROWS * DIM + 255) / 256, 256>>>(x, xhi, MROWS * DIM);
    {
        dim3 g1(HGCOLS / 32, DIM / 32);
        transpose_split_tiled<<<g1, 256>>>(W_hg, whgT_hi, whgT_lo, DIM, HGCOLS);
        dim3 g2(DIM / 32, DI / 32);
        transpose_split_tiled<<<g2, 256>>>(W_out, woutT_hi, woutT_lo, DI, DIM);
    }

    // GEMM1: hg[16384,4096] = x @ W_hg
    {
        dim3 grid(HGCOLS / BN, MROWS / BM);
        hmma_gemm<<<grid, 256, GEMM_DYNSMEM>>>(xhi, whgT_hi, whgT_lo, hg_ptr, HGCOLS, DIM);
    }

    scan_pass1<<<(NCH * NCHUNK) / 256, 256>>>();
    scan_mid<<<NCH / 256, 256>>>();
    scan_pass2<<<(NCH * NCHUNK) / 256, 256>>>();

    // GEMM2: out[16384,1024] = h @ W_out
    {
        dim3 grid(DIM / BN, MROWS / BM);
        hmma_gemm<<<grid, 256, GEMM_DYNSMEM>>>(hhi, woutT_hi, woutT_lo, out, DIM, DI);
    }
}

// round 11
// speedup vs baseline: 2.1874x; 1.5035x over previous
#include <cuda_runtime.h>
#include <cuda_fp16.h>
#include <math.h>
#include <stdint.h>

// ---------------- problem constants ----------------
#define BATCH   4
#define SEQ     4096
#define DIM     1024
#define DI      2048
#define HGCOLS  4096
#define MROWS   16384
#define NCH     8192
#define CHUNK   128
#define NCHUNK  32

// ---------------- scratch ----------------
__device__ float g_hg[(size_t)MROWS * HGCOLS];        // 256 MB
__device__ __half g_xhi[(size_t)MROWS * DIM];
__device__ __half g_whgT[(size_t)HGCOLS * DIM];       // [N,K]
__device__ __half g_woutT[(size_t)DIM * DI];          // [N,K]
__device__ __half g_hhi[(size_t)MROWS * DI];
__device__ float g_A[NCH * NCHUNK];
__device__ float g_M[NCH * NCHUNK];
__device__ float g_W[NCH * NCHUNK];

// ---------------- PTX helpers ----------------
__device__ __forceinline__ uint32_t smem_u32(const void* p) {
    uint32_t a;
    asm("{ .reg .u64 t; cvta.to.shared.u64 t, %1; cvt.u32.u64 %0, t; }" : "=r"(a) : "l"(p));
    return a;
}
__device__ __forceinline__ void cp16(uint32_t dst, const void* src) {
    asm volatile("cp.async.cg.shared.global [%0], [%1], 16;" :: "r"(dst), "l"(src));
}
#define CP_COMMIT() asm volatile("cp.async.commit_group;" ::: "memory")
#define CP_WAIT0()  asm volatile("cp.async.wait_group 0;" ::: "memory")

#define LDSM4(r, a) asm volatile( \
    "ldmatrix.sync.aligned.m8n8.x4.shared.b16 {%0,%1,%2,%3}, [%4];" \
    : "=r"((r)[0]), "=r"((r)[1]), "=r"((r)[2]), "=r"((r)[3]) : "r"(a))
#define LDSM2(r, a) asm volatile( \
    "ldmatrix.sync.aligned.m8n8.x2.shared.b16 {%0,%1}, [%2];" \
    : "=r"((r)[0]), "=r"((r)[1]) : "r"(a))
#define MMA16816(c, a, b) asm volatile( \
    "mma.sync.aligned.m16n8k16.row.col.f32.f16.f16.f32 " \
    "{%0,%1,%2,%3},{%4,%5,%6,%7},{%8,%9},{%0,%1,%2,%3};" \
    : "+f"((c)[0]), "+f"((c)[1]), "+f"((c)[2]), "+f"((c)[3]) \
    : "r"((a)[0]), "r"((a)[1]), "r"((a)[2]), "r"((a)[3]), "r"((b)[0]), "r"((b)[1]))

// ---------------- HMMA GEMM: C[M,N] = A[M,K] @ B[N,K]^T, single fp16 product ----------------
#define BM 128
#define BN 128
#define BK 32
#define SSTRIDE_H 40                     // halves per smem row (32 + 8 pad)
#define LIMB_BYTES (128 * SSTRIDE_H * 2) // 10240
#define STAGE_BYTES (2 * LIMB_BYTES)     // A, B = 20480
#define GEMM_DYNSMEM (2 * STAGE_BYTES)   // 40960

__global__ __launch_bounds__(256, 2)
void hmma_gemm(const __half* __restrict__ Ahi,
               const __half* __restrict__ Bhi,
               float* __restrict__ C, int N, int K) {
    extern __shared__ char dynsmem[];
    const uint32_t sbase = smem_u32(dynsmem);

    const int tid  = threadIdx.x;
    const int wid  = tid >> 5;
    const int lane = tid & 31;
    const int wm   = wid >> 2;
    const int wn   = wid & 3;
    const int m0   = blockIdx.y * BM;
    const int n0   = blockIdx.x * BN;
    const int NI   = K / BK;

    const int arow_l = (lane & 7) + ((lane & 8) ? 8 : 0);
    const int acol_l = (lane >> 4) * 8;
    const int blane  = lane & 15;
    const int brow_l = blane & 7;
    const int bcol_l = (blane >> 3) * 8;

    float acc[4][4][4];
    #pragma unroll
    for (int i = 0; i < 4; i++)
        #pragma unroll
        for (int j = 0; j < 4; j++)
            #pragma unroll
            for (int q = 0; q < 4; q++) acc[i][j][q] = 0.f;

    auto prefetch = [&](int it, int s) {
        const uint32_t sb = sbase + s * STAGE_BYTES;
        const int kt = it * BK;
        #pragma unroll
        for (int t = tid; t < 512; t += 256) {
            const int row = t >> 2;
            const int seg = t & 3;
            const uint32_t so = (uint32_t)(row * (SSTRIDE_H * 2) + seg * 16);
            const size_t ga = (size_t)(m0 + row) * K + kt + seg * 8;
            const size_t gb = (size_t)(n0 + row) * K + kt + seg * 8;
            cp16(sb + so,              Ahi + ga);
            cp16(sb + LIMB_BYTES + so, Bhi + gb);
        }
        CP_COMMIT();
    };

    prefetch(0, 0);

    for (int it = 0; it < NI; it++) {
        const int s = it & 1;
        CP_WAIT0();
        __syncthreads();   // single barrier: stage s loaded AND stage s^1 free
        if (it + 1 < NI) prefetch(it + 1, s ^ 1);

        const uint32_t sAh = sbase + s * STAGE_BYTES;
        const uint32_t sBh = sAh + LIMB_BYTES;

        #pragma unroll
        for (int ks = 0; ks < 2; ks++) {
            uint32_t af[4][4], bh[4][2];
            #pragma unroll
            for (int mf = 0; mf < 4; mf++) {
                const uint32_t ao =
                    (uint32_t)((wm * 64 + mf * 16 + arow_l) * (SSTRIDE_H * 2) +
                               (ks * 16 + acol_l) * 2);
                LDSM4(af[mf], sAh + ao);
            }
            #pragma unroll
            for (int nf = 0; nf < 4; nf++) {
                const uint32_t bo =
                    (uint32_t)((wn * 32 + nf * 8 + brow_l) * (SSTRIDE_H * 2) +
                               (ks * 16 + bcol_l) * 2);
                LDSM2(bh[nf], sBh + bo);
            }
            #pragma unroll
            for (int mf = 0; mf < 4; mf++)
                #pragma unroll
                for (int nf = 0; nf < 4; nf++) MMA16816(acc[mf][nf], af[mf], bh[nf]);
        }
    }

    // epilogue
    #pragma unroll
    for (int mf = 0; mf < 4; mf++) {
        const int r0 = m0 + wm * 64 + mf * 16 + lane / 4;
        #pragma unroll
        for (int nf = 0; nf < 4; nf++) {
            const int col = n0 + wn * 32 + nf * 8 + 2 * (lane % 4);
            *(float2*)(C + (size_t)r0 * N + col) =
                make_float2(acc[mf][nf][0], acc[mf][nf][1]);
            *(float2*)(C + (size_t)(r0 + 8) * N + col) =
                make_float2(acc[mf][nf][2], acc[mf][nf][3]);
        }
    }
}

// ---------------- prep ----------------
__global__ __launch_bounds__(256)
void cast_hi(const float* __restrict__ in, __half* __restrict__ hi, int n) {
    int i = blockIdx.x * blockDim.x + threadIdx.x;
    if (i >= n) return;
    hi[i] = __float2half_rn(in[i]);
}

// W[K,N] row-major -> out[N,K] row-major fp16, 32x32 smem tiles
__global__ __launch_bounds__(256)
void transpose_cast_tiled(const float* __restrict__ W, __half* __restrict__ hi,
                          int K, int N) {
    __shared__ float tile[32][33];
    const int k0 = blockIdx.y * 32;
    const int n0 = blockIdx.x * 32;
    const int tx = threadIdx.x & 31;
    const int ty = threadIdx.x >> 5;   // 0..7

    #pragma unroll
    for (int r = 0; r < 4; r++) {
        const int k = k0 + ty + r * 8;
        tile[ty + r * 8][tx] = W[(size_t)k * N + n0 + tx];
    }
    __syncthreads();
    #pragma unroll
    for (int r = 0; r < 4; r++) {
        const int n = n0 + ty + r * 8;
        hi[(size_t)n * K + k0 + tx] = __float2half_rn(tile[tx][ty + r * 8]);
    }
}

// ---------------- scan (scalar, proven form) ----------------
__device__ __forceinline__ void minGRU_terms(float hid, float g, float& lc, float& lv) {
    float sp = log1pf(__expf(-fabsf(g))) + fmaxf(g, 0.f);
    lc = -sp;
    float log_z = g - sp;
    lv = __logf(fmaxf(hid, 0.f) + 0.5f) + log_z;
}

__global__ __launch_bounds__(256)
void scan_pass1() {
    int tid = blockIdx.x * blockDim.x + threadIdx.x;
    int e = tid % DI;
    int c = (tid / DI) % NCHUNK;
    int b = tid / (DI * NCHUNK);

    const float* base = g_hg + ((size_t)(b * SEQ + c * CHUNK)) * HGCOLS + e;
    float a = 0.f, m = -INFINITY, s = 0.f;
    for (int t = 0; t < CHUNK; t++) {
        float hid = base[(size_t)t * HGCOLS];
        float g   = base[(size_t)t * HGCOLS + DI];
        float lc, lv;
        minGRU_terms(hid, g, lc, lv);
        a += lc;
        float v = lv - a;
        if (v <= m) {
            s += __expf(v - m);
        } else {
            s = s * __expf(m - v) + 1.f;
            m = v;
        }
    }
    int o = (b * NCHUNK + c) * DI + e;
    g_A[o] = a;
    g_M[o] = m + __logf(s);
}

__global__ __launch_bounds__(256)
void scan_mid() {
    int tid = blockIdx.x * blockDim.x + threadIdx.x;
    int e = tid % DI;
    int b = tid / DI;
    float W = -INFINITY;
    for (int c = 0; c < NCHUNK; c++) {
        int o = (b * NCHUNK + c) * DI + e;
        g_W[o] = W;
        float A = g_A[o], M = g_M[o];
        float mx = fmaxf(W, M);
        float mn = fminf(W, M);
        float r = (mx == -INFINITY) ? -INFINITY : mx + log1pf(__expf(mn - mx));
        W = A + r;
    }
}

__global__ __launch_bounds__(256)
void scan_pass2() {
    int tid = blockIdx.x * blockDim.x + threadIdx.x;
    int e = tid % DI;
    int c = (tid / DI) % NCHUNK;
    int b = tid / (DI * NCHUNK);

    const float* base = g_hg + ((size_t)(b * SEQ + c * CHUNK)) * HGCOLS + e;
    size_t hidx = ((size_t)(b * SEQ + c * CHUNK)) * DI + e;
    float W = g_W[(b * NCHUNK + c) * DI + e];

    float a = 0.f, m = -INFINITY, s = 0.f;
    for (int t = 0; t < CHUNK; t++) {
        float hid = base[(size_t)t * HGCOLS];
        float g   = base[(size_t)t * HGCOLS + DI];
        float lc, lv;
        minGRU_terms(hid, g, lc, lv);
        a += lc;
        float v = lv - a;
        if (v <= m) {
            s += __expf(v - m);
        } else {
            s = s * __expf(m - v) + 1.f;
            m = v;
        }
        float hv = __expf(a + W) + __expf(a + m) * s;
        g_hhi[hidx + (size_t)t * DI] = __float2half_rn(hv);
    }
}

// ---------------- launch ----------------
extern "C" void kernel_launch(void* const* d_in, const int* in_sizes, int n_in,
                              void* d_out, int out_size) {
    const float* x     = (const float*)d_in[0];
    const float* W_hg  = (const float*)d_in[1];
    const float* W_out = (const float*)d_in[2];
    float* out = (float*)d_out;

    float* hg_ptr;
    __half *xhi, *whgT, *woutT, *hhi;
    cudaGetSymbolAddress((void**)&hg_ptr, g_hg);
    cudaGetSymbolAddress((void**)&xhi, g_xhi);
    cudaGetSymbolAddress((void**)&whgT, g_whgT);
    cudaGetSymbolAddress((void**)&woutT, g_woutT);
    cudaGetSymbolAddress((void**)&hhi, g_hhi);

    cudaFuncSetAttribute(hmma_gemm, cudaFuncAttributeMaxDynamicSharedMemorySize, GEMM_DYNSMEM);

    cast_hi<<<(MROWS * DIM + 255) / 256, 256>>>(x, xhi, MROWS * DIM);
    {
        dim3 g1(HGCOLS / 32, DIM / 32);
        transpose_cast_tiled<<<g1, 256>>>(W_hg, whgT, DIM, HGCOLS);
        dim3 g2(DIM / 32, DI / 32);
        transpose_cast_tiled<<<g2, 256>>>(W_out, woutT, DI, DIM);
    }

    // GEMM1: hg[16384,4096] = x @ W_hg
    {
        dim3 grid(HGCOLS / BN, MROWS / BM);
        hmma_gemm<<<grid, 256, GEMM_DYNSMEM>>>(xhi, whgT, hg_ptr, HGCOLS, DIM);
    }

    scan_pass1<<<(NCH * NCHUNK) / 256, 256>>>();
    scan_mid<<<NCH / 256, 256>>>();
    scan_pass2<<<(NCH * NCHUNK) / 256, 256>>>();

    // GEMM2: out[16384,1024] = h @ W_out
    {
        dim3 grid(DIM / BN, MROWS / BM);
        hmma_gemm<<<grid, 256, GEMM_DYNSMEM>>>(hhi, woutT, out, DIM, DI);
    }
}

// round 12
// speedup vs baseline: 2.3704x; 1.0836x over previous
#include <cuda_runtime.h>
#include <cuda_fp16.h>
#include <math.h>
#include <stdint.h>

// ---------------- problem constants ----------------
#define BATCH   4
#define SEQ     4096
#define DIM     1024
#define DI      2048
#define HGCOLS  4096
#define MROWS   16384
#define NCH     8192
#define CHUNK   128
#define NCHUNK  32

// ---------------- scratch ----------------
__device__ float g_hg[(size_t)MROWS * HGCOLS];        // 256 MB
__device__ __half g_xhi[(size_t)MROWS * DIM];
__device__ __half g_whgT[(size_t)HGCOLS * DIM];       // [N,K]
__device__ __half g_woutT[(size_t)DIM * DI];          // [N,K]
__device__ __half g_hhi[(size_t)MROWS * DI];
__device__ float g_A[NCH * NCHUNK];
__device__ float g_M[NCH * NCHUNK];
__device__ float g_W[NCH * NCHUNK];

// ---------------- PTX helpers ----------------
__device__ __forceinline__ uint32_t smem_u32(const void* p) {
    uint32_t a;
    asm("{ .reg .u64 t; cvta.to.shared.u64 t, %1; cvt.u32.u64 %0, t; }" : "=r"(a) : "l"(p));
    return a;
}
__device__ __forceinline__ void cp16(uint32_t dst, const void* src) {
    asm volatile("cp.async.cg.shared.global [%0], [%1], 16;" :: "r"(dst), "l"(src));
}
#define CP_COMMIT() asm volatile("cp.async.commit_group;" ::: "memory")
#define CP_WAIT0()  asm volatile("cp.async.wait_group 0;" ::: "memory")

#define LDSM4(r, a) asm volatile( \
    "ldmatrix.sync.aligned.m8n8.x4.shared.b16 {%0,%1,%2,%3}, [%4];" \
    : "=r"((r)[0]), "=r"((r)[1]), "=r"((r)[2]), "=r"((r)[3]) : "r"(a))
#define LDSM2(r, a) asm volatile( \
    "ldmatrix.sync.aligned.m8n8.x2.shared.b16 {%0,%1}, [%2];" \
    : "=r"((r)[0]), "=r"((r)[1]) : "r"(a))
#define MMA16816(c, a, b) asm volatile( \
    "mma.sync.aligned.m16n8k16.row.col.f32.f16.f16.f32 " \
    "{%0,%1,%2,%3},{%4,%5,%6,%7},{%8,%9},{%0,%1,%2,%3};" \
    : "+f"((c)[0]), "+f"((c)[1]), "+f"((c)[2]), "+f"((c)[3]) \
    : "r"((a)[0]), "r"((a)[1]), "r"((a)[2]), "r"((a)[3]), "r"((b)[0]), "r"((b)[1]))

// ---------------- HMMA GEMM: C[M,N] = A[M,K] @ B[N,K]^T, single fp16 product, BK=64 ----------------
#define BM 128
#define BN 128
#define BK 64
#define SSTRIDE_H 72                     // halves per smem row (64 + 8 pad)
#define LIMB_BYTES (128 * SSTRIDE_H * 2) // 18432
#define STAGE_BYTES (2 * LIMB_BYTES)     // A, B = 36864
#define GEMM_DYNSMEM (2 * STAGE_BYTES)   // 73728

__global__ __launch_bounds__(256, 2)
void hmma_gemm(const __half* __restrict__ Ahi,
               const __half* __restrict__ Bhi,
               float* __restrict__ C, int N, int K) {
    extern __shared__ char dynsmem[];
    const uint32_t sbase = smem_u32(dynsmem);

    const int tid  = threadIdx.x;
    const int wid  = tid >> 5;
    const int lane = tid & 31;
    const int wm   = wid >> 2;
    const int wn   = wid & 3;
    const int m0   = blockIdx.y * BM;
    const int n0   = blockIdx.x * BN;
    const int NI   = K / BK;

    const int arow_l = (lane & 7) + ((lane & 8) ? 8 : 0);
    const int acol_l = (lane >> 4) * 8;
    const int blane  = lane & 15;
    const int brow_l = blane & 7;
    const int bcol_l = (blane >> 3) * 8;

    float acc[4][4][4];
    #pragma unroll
    for (int i = 0; i < 4; i++)
        #pragma unroll
        for (int j = 0; j < 4; j++)
            #pragma unroll
            for (int q = 0; q < 4; q++) acc[i][j][q] = 0.f;

    auto prefetch = [&](int it, int s) {
        const uint32_t sb = sbase + s * STAGE_BYTES;
        const int kt = it * BK;
        #pragma unroll
        for (int t = tid; t < 1024; t += 256) {
            const int row = t >> 3;          // 0..127
            const int seg = t & 7;           // 8 x 16B = 128B = 64 halves
            const uint32_t so = (uint32_t)(row * (SSTRIDE_H * 2) + seg * 16);
            const size_t ga = (size_t)(m0 + row) * K + kt + seg * 8;
            const size_t gb = (size_t)(n0 + row) * K + kt + seg * 8;
            cp16(sb + so,              Ahi + ga);
            cp16(sb + LIMB_BYTES + so, Bhi + gb);
        }
        CP_COMMIT();
    };

    prefetch(0, 0);

    for (int it = 0; it < NI; it++) {
        const int s = it & 1;
        CP_WAIT0();
        __syncthreads();   // single barrier: stage s loaded AND stage s^1 free
        if (it + 1 < NI) prefetch(it + 1, s ^ 1);

        const uint32_t sAh = sbase + s * STAGE_BYTES;
        const uint32_t sBh = sAh + LIMB_BYTES;

        #pragma unroll
        for (int ks = 0; ks < 4; ks++) {
            uint32_t af[4][4], bh[4][2];
            #pragma unroll
            for (int mf = 0; mf < 4; mf++) {
                const uint32_t ao =
                    (uint32_t)((wm * 64 + mf * 16 + arow_l) * (SSTRIDE_H * 2) +
                               (ks * 16 + acol_l) * 2);
                LDSM4(af[mf], sAh + ao);
            }
            #pragma unroll
            for (int nf = 0; nf < 4; nf++) {
                const uint32_t bo =
                    (uint32_t)((wn * 32 + nf * 8 + brow_l) * (SSTRIDE_H * 2) +
                               (ks * 16 + bcol_l) * 2);
                LDSM2(bh[nf], sBh + bo);
            }
            #pragma unroll
            for (int mf = 0; mf < 4; mf++)
                #pragma unroll
                for (int nf = 0; nf < 4; nf++) MMA16816(acc[mf][nf], af[mf], bh[nf]);
        }
    }

    // epilogue
    #pragma unroll
    for (int mf = 0; mf < 4; mf++) {
        const int r0 = m0 + wm * 64 + mf * 16 + lane / 4;
        #pragma unroll
        for (int nf = 0; nf < 4; nf++) {
            const int col = n0 + wn * 32 + nf * 8 + 2 * (lane % 4);
            *(float2*)(C + (size_t)r0 * N + col) =
                make_float2(acc[mf][nf][0], acc[mf][nf][1]);
            *(float2*)(C + (size_t)(r0 + 8) * N + col) =
                make_float2(acc[mf][nf][2], acc[mf][nf][3]);
        }
    }
}

// ---------------- prep ----------------
__global__ __launch_bounds__(256)
void cast_hi(const float* __restrict__ in, __half* __restrict__ hi, int n) {
    int i = blockIdx.x * blockDim.x + threadIdx.x;
    if (i >= n) return;
    hi[i] = __float2half_rn(in[i]);
}

// W[K,N] row-major -> out[N,K] row-major fp16, 32x32 smem tiles
__global__ __launch_bounds__(256)
void transpose_cast_tiled(const float* __restrict__ W, __half* __restrict__ hi,
                          int K, int N) {
    __shared__ float tile[32][33];
    const int k0 = blockIdx.y * 32;
    const int n0 = blockIdx.x * 32;
    const int tx = threadIdx.x & 31;
    const int ty = threadIdx.x >> 5;   // 0..7

    #pragma unroll
    for (int r = 0; r < 4; r++) {
        const int k = k0 + ty + r * 8;
        tile[ty + r * 8][tx] = W[(size_t)k * N + n0 + tx];
    }
    __syncthreads();
    #pragma unroll
    for (int r = 0; r < 4; r++) {
        const int n = n0 + ty + r * 8;
        hi[(size_t)n * K + k0 + tx] = __float2half_rn(tile[tx][ty + r * 8]);
    }
}

// ---------------- scan (scalar, proven form) ----------------
__device__ __forceinline__ void minGRU_terms(float hid, float g, float& lc, float& lv) {
    float sp = log1pf(__expf(-fabsf(g))) + fmaxf(g, 0.f);
    lc = -sp;
    float log_z = g - sp;
    lv = __logf(fmaxf(hid, 0.f) + 0.5f) + log_z;
}

__global__ __launch_bounds__(256)
void scan_pass1() {
    int tid = blockIdx.x * blockDim.x + threadIdx.x;
    int e = tid % DI;
    int c = (tid / DI) % NCHUNK;
    int b = tid / (DI * NCHUNK);

    const float* base = g_hg + ((size_t)(b * SEQ + c * CHUNK)) * HGCOLS + e;
    float a = 0.f, m = -INFINITY, s = 0.f;
    for (int t = 0; t < CHUNK; t++) {
        float hid = base[(size_t)t * HGCOLS];
        float g   = base[(size_t)t * HGCOLS + DI];
        float lc, lv;
        minGRU_terms(hid, g, lc, lv);
        a += lc;
        float v = lv - a;
        if (v <= m) {
            s += __expf(v - m);
        } else {
            s = s * __expf(m - v) + 1.f;
            m = v;
        }
    }
    int o = (b * NCHUNK + c) * DI + e;
    g_A[o] = a;
    g_M[o] = m + __logf(s);
}

__global__ __launch_bounds__(256)
void scan_mid() {
    int tid = blockIdx.x * blockDim.x + threadIdx.x;
    int e = tid % DI;
    int b = tid / DI;
    float W = -INFINITY;
    for (int c = 0; c < NCHUNK; c++) {
        int o = (b * NCHUNK + c) * DI + e;
        g_W[o] = W;
        float A = g_A[o], M = g_M[o];
        float mx = fmaxf(W, M);
        float mn = fminf(W, M);
        float r = (mx == -INFINITY) ? -INFINITY : mx + log1pf(__expf(mn - mx));
        W = A + r;
    }
}

__global__ __launch_bounds__(256)
void scan_pass2() {
    int tid = blockIdx.x * blockDim.x + threadIdx.x;
    int e = tid % DI;
    int c = (tid / DI) % NCHUNK;
    int b = tid / (DI * NCHUNK);

    const float* base = g_hg + ((size_t)(b * SEQ + c * CHUNK)) * HGCOLS + e;
    size_t hidx = ((size_t)(b * SEQ + c * CHUNK)) * DI + e;
    float W = g_W[(b * NCHUNK + c) * DI + e];

    float a = 0.f, m = -INFINITY, s = 0.f;
    for (int t = 0; t < CHUNK; t++) {
        float hid = base[(size_t)t * HGCOLS];
        float g   = base[(size_t)t * HGCOLS + DI];
        float lc, lv;
        minGRU_terms(hid, g, lc, lv);
        a += lc;
        float v = lv - a;
        if (v <= m) {
            s += __expf(v - m);
        } else {
            s = s * __expf(m - v) + 1.f;
            m = v;
        }
        float hv = __expf(a + W) + __expf(a + m) * s;
        g_hhi[hidx + (size_t)t * DI] = __float2half_rn(hv);
    }
}

// ---------------- launch ----------------
extern "C" void kernel_launch(void* const* d_in, const int* in_sizes, int n_in,
                              void* d_out, int out_size) {
    const float* x     = (const float*)d_in[0];
    const float* W_hg  = (const float*)d_in[1];
    const float* W_out = (const float*)d_in[2];
    float* out = (float*)d_out;

    float* hg_ptr;
    __half *xhi, *whgT, *woutT, *hhi;
    cudaGetSymbolAddress((void**)&hg_ptr, g_hg);
    cudaGetSymbolAddress((void**)&xhi, g_xhi);
    cudaGetSymbolAddress((void**)&whgT, g_whgT);
    cudaGetSymbolAddress((void**)&woutT, g_woutT);
    cudaGetSymbolAddress((void**)&hhi, g_hhi);

    cudaFuncSetAttribute(hmma_gemm, cudaFuncAttributeMaxDynamicSharedMemorySize, GEMM_DYNSMEM);

    cast_hi<<<(MROWS * DIM + 255) / 256, 256>>>(x, xhi, MROWS * DIM);
    {
        dim3 g1(HGCOLS / 32, DIM / 32);
        transpose_cast_tiled<<<g1, 256>>>(W_hg, whgT, DIM, HGCOLS);
        dim3 g2(DIM / 32, DI / 32);
        transpose_cast_tiled<<<g2, 256>>>(W_out, woutT, DI, DIM);
    }

    // GEMM1: hg[16384,4096] = x @ W_hg
    {
        dim3 grid(HGCOLS / BN, MROWS / BM);
        hmma_gemm<<<grid, 256, GEMM_DYNSMEM>>>(xhi, whgT, hg_ptr, HGCOLS, DIM);
    }

    scan_pass1<<<(NCH * NCHUNK) / 256, 256>>>();
    scan_mid<<<NCH / 256, 256>>>();
    scan_pass2<<<(NCH * NCHUNK) / 256, 256>>>();

    // GEMM2: out[16384,1024] = h @ W_out
    {
        dim3 grid(DIM / BN, MROWS / BM);
        hmma_gemm<<<grid, 256, GEMM_DYNSMEM>>>(hhi, woutT, out, DIM, DI);
    }
}